// round 14
// baseline (speedup 1.0000x reference)
#include <cuda_runtime.h>
#include <cuda.h>
#include <cstdint>
#include <math.h>

// B=64, S=512, Q=800, K=4, D=64  ->  GEMM: C[M=32768, N=64] = A[M,800] * Wq^T[800,64]
#define MDIM    32768
#define KDIM    800
#define NDIM    64
#define TM      128
#define TK      32
#define NIT     25
#define THREADS 256
#define STAGES  4

#define A_BYTES (TM * TK * 4)            // 16384
#define B_BYTES (NDIM * TK * 4)          //  8192
#define STAGE_BYTES (A_BYTES + B_BYTES)  // 24576
#define OFF_FULL   (STAGES * STAGE_BYTES)        // 98304  (4 x 8B)
#define OFF_EMPTY  (OFF_FULL + 32)               // 98336  (4 x 8B)
#define SMEM_TOTAL (OFF_EMPTY + 32)              // 98368

// Pre-converted tf32 B, per 32-k stage in the exact swizzled smem image:
// word (n, kk) of stage s at  s*2048 + n*32 + (kk ^ ((n&7)*4))
__device__ uint32_t g_Bt[NIT * NDIM * TK];   // 204.8 KB

// ---------------------------------------------------------------------------
// helpers
// ---------------------------------------------------------------------------
__device__ __forceinline__ uint32_t f2tf(float x) {
    uint32_t r;
    asm("cvt.rna.tf32.f32 %0, %1;" : "=r"(r) : "f"(x));
    return r;
}
__device__ __forceinline__ uint32_t u2tf(uint32_t bits) {
    return f2tf(__uint_as_float(bits));
}

__device__ __forceinline__ void ldsm4(uint32_t& r0, uint32_t& r1, uint32_t& r2, uint32_t& r3,
                                      uint32_t addr) {
    asm volatile("ldmatrix.sync.aligned.m8n8.x4.shared.b16 {%0,%1,%2,%3}, [%4];"
                 : "=r"(r0), "=r"(r1), "=r"(r2), "=r"(r3) : "r"(addr));
}

__device__ __forceinline__ void mma_tf32(float* c,
                                         uint32_t a0, uint32_t a1, uint32_t a2, uint32_t a3,
                                         uint32_t b0, uint32_t b1) {
    asm volatile(
        "mma.sync.aligned.m16n8k8.row.col.f32.tf32.tf32.f32 "
        "{%0,%1,%2,%3}, {%4,%5,%6,%7}, {%8,%9}, {%0,%1,%2,%3};"
        : "+f"(c[0]), "+f"(c[1]), "+f"(c[2]), "+f"(c[3])
        : "r"(a0), "r"(a1), "r"(a2), "r"(a3), "r"(b0), "r"(b1));
}

__device__ __forceinline__ void mbar_wait(uint32_t mbar, uint32_t parity) {
    asm volatile(
        "{\n\t"
        ".reg .pred P1;\n\t"
        "WAIT_LOOP_%=:\n\t"
        "mbarrier.try_wait.parity.acquire.cta.shared::cta.b64 P1, [%0], %1, 0x989680;\n\t"
        "@P1 bra.uni WAIT_DONE_%=;\n\t"
        "bra.uni WAIT_LOOP_%=;\n\t"
        "WAIT_DONE_%=:\n\t"
        "}"
        :: "r"(mbar), "r"(parity) : "memory");
}

// ---------------------------------------------------------------------------
// pre-kernel: Wq -> tf32, swizzled smem image (per 32-k stage)
// ---------------------------------------------------------------------------
__global__ void convert_B_kernel(const float* __restrict__ Wq) {
    int i = blockIdx.x * 256 + threadIdx.x;
    if (i < NIT * 2048) {
        int s  = i >> 11;
        int wd = i & 2047;
        int n  = wd >> 5;
        int kk = (wd & 31) ^ ((n & 7) * 4);
        g_Bt[i] = f2tf(Wq[n * KDIM + s * TK + kk]);
    }
}

// ---------------------------------------------------------------------------
// main kernel: 8 free-running warps (16 rows x 64 cols each), mbarrier
// producer/consumer pipeline, no __syncthreads in the main loop.
// ---------------------------------------------------------------------------
__global__ __launch_bounds__(THREADS, 2)
void ordinal_embed_kernel(const __grid_constant__ CUtensorMap tmapA,
                          const __grid_constant__ CUtensorMap tmapB,
                          const int*   __restrict__ rdat,
                          const float* __restrict__ bq,   // [64]
                          const float* __restrict__ Wr,   // [4]
                          const float* __restrict__ br,   // [1]
                          float*       __restrict__ out)  // [32768, 64]
{
    extern __shared__ uint8_t smem[];
    const uint32_t smemBase = (uint32_t)__cvta_generic_to_shared(smem);

    const int tid  = threadIdx.x;
    const int lane = tid & 31;
    const int w    = tid >> 5;         // warp 0..7 -> rows [w*16, w*16+16)
    const int bm   = blockIdx.x;

    float acc[8][4];
    #pragma unroll
    for (int nt = 0; nt < 8; ++nt)
        #pragma unroll
        for (int i = 0; i < 4; ++i)
            acc[nt][i] = 0.0f;

    // ---- barrier init: full[s] count=1 (producer), empty[s] count=8 (warps)
    if (tid == 0) {
        #pragma unroll
        for (int s = 0; s < STAGES; ++s) {
            asm volatile("mbarrier.init.shared.b64 [%0], %1;"
                         :: "r"(smemBase + OFF_FULL + s * 8), "r"(1u) : "memory");
            asm volatile("mbarrier.init.shared.b64 [%0], %1;"
                         :: "r"(smemBase + OFF_EMPTY + s * 8), "r"(8u) : "memory");
        }
        asm volatile("fence.proxy.async.shared::cta;" ::: "memory");
    }
    __syncthreads();

    // ---- producer: wait empty, then one TMA pair per stage ------------------
    // empty parity for stage-use index u = it>>2 is (u^1)&1 (init-flip: the
    // first STAGES waits pass immediately on a fresh barrier).
    #define STAGE(IT)                                                            \
    do {                                                                         \
        const int _s = (IT) % STAGES;                                            \
        const uint32_t _mb = smemBase + OFF_FULL + _s * 8;                       \
        const uint32_t _sb = smemBase + _s * STAGE_BYTES;                        \
        mbar_wait(smemBase + OFF_EMPTY + _s * 8,                                 \
                  (uint32_t)((((IT) >> 2) ^ 1) & 1));                            \
        asm volatile("mbarrier.arrive.expect_tx.shared.b64 _, [%0], %1;"         \
                     :: "r"(_mb), "r"((uint32_t)STAGE_BYTES) : "memory");        \
        asm volatile(                                                            \
            "cp.async.bulk.tensor.2d.shared::cta.global.tile"                    \
            ".mbarrier::complete_tx::bytes [%0], [%1, {%2, %3}], [%4];"          \
            :: "r"(_sb), "l"(&tmapA), "r"((IT) * TK), "r"(bm * TM),              \
               "r"(_mb) : "memory");                                             \
        asm volatile(                                                            \
            "cp.async.bulk.tensor.2d.shared::cta.global.tile"                    \
            ".mbarrier::complete_tx::bytes [%0], [%1, {%2, %3}], [%4];"          \
            :: "r"(_sb + A_BYTES), "l"(&tmapB), "r"(0), "r"((IT) * 8),           \
               "r"(_mb) : "memory");                                             \
    } while (0)

    // ---- ldmatrix lane coordinates -----------------------------------------
    const int rA = w * 16 + (lane & 15);
    const int cA = (lane >> 4) << 2;       // 0 or 4
    const int xA = (rA & 7) * 4;
    const int nBlow = (lane & 7) + ((lane >> 4) & 1) * 8;   // + p*16
    const int cB    = ((lane >> 3) & 1) * 4;                // 0 or 4

    if (tid == 0) { STAGE(0); STAGE(1); STAGE(2); }

    for (int it = 0; it < NIT; ++it) {
        // producer leg (warp 0 lane 0): issue stage it+3
        if (tid == 0 && it + STAGES - 1 < NIT) STAGE(it + STAGES - 1);

        // consumer leg: wait for stage it's data (acquire)
        mbar_wait(smemBase + OFF_FULL + (it % STAGES) * 8,
                  (uint32_t)((it >> 2) & 1));

        const uint32_t sb = smemBase + (it % STAGES) * STAGE_BYTES;
        const uint32_t aB = sb;
        const uint32_t bB = sb + A_BYTES;

        #pragma unroll
        for (int k8 = 0; k8 < 4; ++k8) {
            uint32_t a0, a1, a2, a3;
            ldsm4(a0, a1, a2, a3,
                  aB + (uint32_t)(rA * TK + ((k8 * 8 + cA) ^ xA)) * 4u);
            a0 = u2tf(a0); a1 = u2tf(a1); a2 = u2tf(a2); a3 = u2tf(a3);

            uint32_t bf[4][4];
            #pragma unroll
            for (int p = 0; p < 4; ++p) {
                int n = p * 16 + nBlow;
                ldsm4(bf[p][0], bf[p][1], bf[p][2], bf[p][3],
                      bB + (uint32_t)(n * TK + ((k8 * 8 + cB) ^ ((n & 7) * 4))) * 4u);
            }

            // release the buffer as soon as the last ldsm of the stage has
            // executed (k8==3); mmas continue on registers afterwards
            if (k8 == 3) {
                __syncwarp();
                if (lane == 0)
                    asm volatile("mbarrier.arrive.shared.b64 _, [%0];"
                                 :: "r"(smemBase + OFF_EMPTY + (it % STAGES) * 8)
                                 : "memory");
            }

            #pragma unroll
            for (int nt = 0; nt < 8; ++nt)
                mma_tf32(acc[nt], a0, a1, a2, a3,
                         bf[nt >> 1][(nt & 1) * 2], bf[nt >> 1][(nt & 1) * 2 + 1]);
        }
    }

    // ---- epilogue: gate(r) * acc + bq (per-warp independent) ---------------
    const float wr0 = Wr[0], wr1 = Wr[1], wr2 = Wr[2], wr3 = Wr[3];
    const float brv = br[0];

    const int rbase = bm * TM + w * 16 + (lane >> 2);
    #pragma unroll
    for (int h = 0; h < 2; ++h) {
        const int row = rbase + h * 8;
        const float rf = (float)rdat[row];
        float s = brv;
        s += fmaxf(1.0f - fabsf(0.0f - rf) * (1.0f / 3.0f), 0.0f) * wr0;
        s += fmaxf(1.0f - fabsf(1.0f - rf) * (1.0f / 3.0f), 0.0f) * wr1;
        s += fmaxf(1.0f - fabsf(2.0f - rf) * (1.0f / 3.0f), 0.0f) * wr2;
        s += fmaxf(1.0f - fabsf(3.0f - rf) * (1.0f / 3.0f), 0.0f) * wr3;
        const float gate = 1.0f / (1.0f + expf(-s));

        #pragma unroll
        for (int nt = 0; nt < 8; ++nt) {
            const int col = nt * 8 + (lane & 3) * 2;
            float2 v;
            v.x = acc[nt][h * 2 + 0] * gate + bq[col];
            v.y = acc[nt][h * 2 + 1] * gate + bq[col + 1];
            *reinterpret_cast<float2*>(out + (size_t)row * NDIM + col) = v;
        }
    }
}

// ---------------------------------------------------------------------------
// launch
// ---------------------------------------------------------------------------
typedef CUresult (*EncodeTiledFn)(
    CUtensorMap*, CUtensorMapDataType, cuuint32_t, void*,
    const cuuint64_t*, const cuuint64_t*, const cuuint32_t*, const cuuint32_t*,
    CUtensorMapInterleave, CUtensorMapSwizzle, CUtensorMapL2promotion,
    CUtensorMapFloatOOBfill);

extern "C" void kernel_launch(void* const* d_in, const int* in_sizes, int n_in,
                              void* d_out, int out_size) {
    const float* q    = (const float*)d_in[0];   // [64,512,800] f32
    const int*   rdat = (const int*)  d_in[1];   // [64,512]     i32
    const float* Wq   = (const float*)d_in[2];   // [64,800]     f32
    const float* bq   = (const float*)d_in[3];   // [64]         f32
    const float* Wr   = (const float*)d_in[4];   // [1,4]        f32
    const float* br   = (const float*)d_in[5];   // [1]          f32
    float* out = (float*)d_out;                  // [64,512,64]  f32

    static EncodeTiledFn encode = nullptr;
    if (!encode) {
        cudaDriverEntryPointQueryResult st;
        void* fn = nullptr;
        cudaGetDriverEntryPoint("cuTensorMapEncodeTiled", &fn,
                                cudaEnableDefault, &st);
        encode = (EncodeTiledFn)fn;
    }

    void* bImg = nullptr;
    cudaGetSymbolAddress(&bImg, g_Bt);

    // A: [KDIM, MDIM] f32, box [32, 128], SW128, L2 promote 256B
    CUtensorMap tmapA{};
    {
        cuuint64_t dims[2]    = {KDIM, MDIM};
        cuuint64_t strides[1] = {KDIM * 4ull};
        cuuint32_t box[2]     = {TK, TM};
        cuuint32_t estr[2]    = {1, 1};
        encode(&tmapA, CU_TENSOR_MAP_DATA_TYPE_FLOAT32, 2, (void*)q,
               dims, strides, box, estr,
               CU_TENSOR_MAP_INTERLEAVE_NONE, CU_TENSOR_MAP_SWIZZLE_128B,
               CU_TENSOR_MAP_L2_PROMOTION_L2_256B,
               CU_TENSOR_MAP_FLOAT_OOB_FILL_NONE);
    }
    // B image: [256, 200] u32, box [256, 8], no swizzle
    CUtensorMap tmapB{};
    {
        cuuint64_t dims[2]    = {256, (cuuint64_t)(NIT * 8)};
        cuuint64_t strides[1] = {256 * 4ull};
        cuuint32_t box[2]     = {256, 8};
        cuuint32_t estr[2]    = {1, 1};
        encode(&tmapB, CU_TENSOR_MAP_DATA_TYPE_FLOAT32, 2, bImg,
               dims, strides, box, estr,
               CU_TENSOR_MAP_INTERLEAVE_NONE, CU_TENSOR_MAP_SWIZZLE_NONE,
               CU_TENSOR_MAP_L2_PROMOTION_L2_256B,
               CU_TENSOR_MAP_FLOAT_OOB_FILL_NONE);
    }

    convert_B_kernel<<<(NIT * 2048 + 255) / 256, 256>>>(Wq);

    cudaFuncSetAttribute(ordinal_embed_kernel,
                         cudaFuncAttributeMaxDynamicSharedMemorySize, SMEM_TOTAL);
    ordinal_embed_kernel<<<MDIM / TM, THREADS, SMEM_TOTAL>>>(
        tmapA, tmapB, rdat, bq, Wr, br, out);
}

// round 15
// speedup vs baseline: 1.0814x; 1.0814x over previous
#include <cuda_runtime.h>
#include <cuda.h>
#include <cuda_fp16.h>
#include <cstdint>
#include <math.h>

// B=64, S=512, Q=800, K=4, D=64  ->  GEMM: C[M=32768, N=64] = A[M,800] * Wq^T[800,64]
#define MDIM    32768
#define KDIM    800
#define NDIM    64
#define TM      128
#define TK      32
#define NIT     25
#define THREADS 256
#define STAGES  4

#define A_BYTES (TM * TK * 4)            // 16384 (raw f32, SW128)
#define B_BYTES (NDIM * TK * 2)          //  4096 (f16 fragment image)
#define STAGE_BYTES (A_BYTES + B_BYTES)  // 20480
#define OFF_MBAR   (STAGES * STAGE_BYTES)        // 81920
#define SMEM_TOTAL (OFF_MBAR + STAGES * 8)       // 81952

// B as f16 mma fragments, lane-indexed for conflict-free LDS.128:
// word idx = ((s*2 + kt)*4 + j)*128 + lane*4 + w   (1024 words / stage)
//   nt = 2j + (w>>1), b = w&1, n = nt*8 + (lane>>2),
//   k = s*32 + kt*16 + b*8 + (lane&3)*2 ; u32 = {hi=f16 Wq[n][k+1], lo=f16 Wq[n][k]}
__device__ uint32_t g_Bt[NIT * 1024];    // 102.4 KB

// ---------------------------------------------------------------------------
// helpers
// ---------------------------------------------------------------------------
__device__ __forceinline__ uint32_t cvt_f16x2(float lo, float hi) {
    uint32_t r;
    asm("cvt.rn.f16x2.f32 %0, %1, %2;" : "=r"(r) : "f"(hi), "f"(lo));
    return r;
}

__device__ __forceinline__ float2 lds64(uint32_t addr) {
    float2 v;
    asm volatile("ld.shared.v2.f32 {%0, %1}, [%2];"
                 : "=f"(v.x), "=f"(v.y) : "r"(addr));
    return v;
}

__device__ __forceinline__ void lds128(uint32_t* r, uint32_t addr) {
    asm volatile("ld.shared.v4.b32 {%0, %1, %2, %3}, [%4];"
                 : "=r"(r[0]), "=r"(r[1]), "=r"(r[2]), "=r"(r[3]) : "r"(addr));
}

__device__ __forceinline__ void mma_f16(float* c,
                                        uint32_t a0, uint32_t a1, uint32_t a2, uint32_t a3,
                                        uint32_t b0, uint32_t b1) {
    asm volatile(
        "mma.sync.aligned.m16n8k16.row.col.f32.f16.f16.f32 "
        "{%0,%1,%2,%3}, {%4,%5,%6,%7}, {%8,%9}, {%0,%1,%2,%3};"
        : "+f"(c[0]), "+f"(c[1]), "+f"(c[2]), "+f"(c[3])
        : "r"(a0), "r"(a1), "r"(a2), "r"(a3), "r"(b0), "r"(b1));
}

__device__ __forceinline__ void mbar_wait(uint32_t mbar, uint32_t parity) {
    asm volatile(
        "{\n\t"
        ".reg .pred P1;\n\t"
        "WAIT_LOOP_%=:\n\t"
        "mbarrier.try_wait.parity.acquire.cta.shared::cta.b64 P1, [%0], %1, 0x989680;\n\t"
        "@P1 bra.uni WAIT_DONE_%=;\n\t"
        "bra.uni WAIT_LOOP_%=;\n\t"
        "WAIT_DONE_%=:\n\t"
        "}"
        :: "r"(mbar), "r"(parity) : "memory");
}

// ---------------------------------------------------------------------------
// pre-kernel: Wq -> f16 fragment image (layout documented above)
// ---------------------------------------------------------------------------
__global__ void convert_B_kernel(const float* __restrict__ Wq) {
    int i = blockIdx.x * 256 + threadIdx.x;
    if (i < NIT * 1024) {
        int w_ = i & 3;
        int l  = (i >> 2) & 31;
        int j  = (i >> 7) & 3;
        int kt = (i >> 9) & 1;
        int s  = i >> 10;
        int nt = j * 2 + (w_ >> 1);
        int b  = w_ & 1;
        int n  = nt * 8 + (l >> 2);
        int k  = s * 32 + kt * 16 + b * 8 + (l & 3) * 2;
        uint32_t lo = __half_as_ushort(__float2half_rn(Wq[n * KDIM + k]));
        uint32_t hi = __half_as_ushort(__float2half_rn(Wq[n * KDIM + k + 1]));
        g_Bt[i] = (hi << 16) | lo;
    }
}

// ---------------------------------------------------------------------------
// main kernel: 8 warps (16 rows x 64 cols each), f16 mma, TMA staging
// ---------------------------------------------------------------------------
__global__ __launch_bounds__(THREADS, 2)
void ordinal_embed_kernel(const __grid_constant__ CUtensorMap tmapA,
                          const __grid_constant__ CUtensorMap tmapB,
                          const int*   __restrict__ rdat,
                          const float* __restrict__ bq,   // [64]
                          const float* __restrict__ Wr,   // [4]
                          const float* __restrict__ br,   // [1]
                          float*       __restrict__ out)  // [32768, 64]
{
    extern __shared__ uint8_t smem[];
    const uint32_t smemBase = (uint32_t)__cvta_generic_to_shared(smem);

    const int tid  = threadIdx.x;
    const int lane = tid & 31;
    const int w    = tid >> 5;         // warp 0..7 -> rows [w*16, w*16+16)
    const int bm   = blockIdx.x;

    float acc[8][4];
    #pragma unroll
    for (int nt = 0; nt < 8; ++nt)
        #pragma unroll
        for (int i = 0; i < 4; ++i)
            acc[nt][i] = 0.0f;

    // ---- mbarrier init ------------------------------------------------------
    if (tid == 0) {
        #pragma unroll
        for (int s = 0; s < STAGES; ++s)
            asm volatile("mbarrier.init.shared.b64 [%0], %1;"
                         :: "r"(smemBase + OFF_MBAR + s * 8), "r"(1u) : "memory");
        asm volatile("fence.proxy.async.shared::cta;" ::: "memory");
    }
    __syncthreads();

    // ---- one-op-per-stage TMA staging --------------------------------------
    #define STAGE(IT)                                                            \
    do {                                                                         \
        if (tid == 0) {                                                          \
            const int _s = (IT) % STAGES;                                        \
            const uint32_t _mb = smemBase + OFF_MBAR + _s * 8;                   \
            const uint32_t _sb = smemBase + _s * STAGE_BYTES;                    \
            asm volatile("mbarrier.arrive.expect_tx.shared.b64 _, [%0], %1;"     \
                         :: "r"(_mb), "r"((uint32_t)STAGE_BYTES) : "memory");    \
            asm volatile(                                                        \
                "cp.async.bulk.tensor.2d.shared::cta.global.tile"                \
                ".mbarrier::complete_tx::bytes [%0], [%1, {%2, %3}], [%4];"      \
                :: "r"(_sb), "l"(&tmapA), "r"((IT) * TK), "r"(bm * TM),          \
                   "r"(_mb) : "memory");                                         \
            asm volatile(                                                        \
                "cp.async.bulk.tensor.2d.shared::cta.global.tile"                \
                ".mbarrier::complete_tx::bytes [%0], [%1, {%2, %3}], [%4];"      \
                :: "r"(_sb + A_BYTES), "l"(&tmapB), "r"(0), "r"((IT) * 4),       \
                   "r"(_mb) : "memory");                                         \
        }                                                                        \
    } while (0)

    // ---- per-lane A fragment coordinates -----------------------------------
    // frag a0: (m = w*16 + lane/4, k = kt*16 + (lane&3)*2), a1: m+8,
    // a2: k+8, a3: m+8,k+8.  Raw A tile is SW128: byte(r,k) = r*128 +
    // ((k*4) ^ ((r&7)*16)); k even -> 8B aligned.
    const int mA  = w * 16 + (lane >> 2);
    const int kpl = (lane & 3) * 2;
    const int xm0 = (mA & 7) * 16;
    const int xm1 = ((mA + 8) & 7) * 16;   // == xm0
    const uint32_t rowOff0 = (uint32_t)mA * 128u;
    const uint32_t rowOff1 = (uint32_t)(mA + 8) * 128u;

    STAGE(0); STAGE(1); STAGE(2);

    for (int it = 0; it < NIT; ++it) {
        mbar_wait(smemBase + OFF_MBAR + (it % STAGES) * 8, (uint32_t)((it >> 2) & 1));
        __syncthreads();   // compute(it-1) complete -> buffer (it+3)%4 reusable

        if (it + STAGES - 1 < NIT) STAGE(it + STAGES - 1);

        const uint32_t sb = smemBase + (it % STAGES) * STAGE_BYTES;
        const uint32_t aB = sb;
        const uint32_t bB = sb + A_BYTES;

        #pragma unroll
        for (int kt = 0; kt < 2; ++kt) {
            // B fragments: 4 conflict-free LDS.128 from the fragment image
            uint32_t bf[4][4];
            #pragma unroll
            for (int j = 0; j < 4; ++j)
                lds128(bf[j], bB + (uint32_t)((kt * 4 + j) * 512 + lane * 16));

            // A fragments: 4 x (LDS.64 + cvt.f16x2)
            const int k0 = kt * 16 + kpl;
            float2 v00 = lds64(aB + rowOff0 + (uint32_t)((k0 * 4) ^ xm0));
            float2 v10 = lds64(aB + rowOff1 + (uint32_t)((k0 * 4) ^ xm1));
            float2 v01 = lds64(aB + rowOff0 + (uint32_t)(((k0 + 8) * 4) ^ xm0));
            float2 v11 = lds64(aB + rowOff1 + (uint32_t)(((k0 + 8) * 4) ^ xm1));
            uint32_t a0 = cvt_f16x2(v00.x, v00.y);
            uint32_t a1 = cvt_f16x2(v10.x, v10.y);
            uint32_t a2 = cvt_f16x2(v01.x, v01.y);
            uint32_t a3 = cvt_f16x2(v11.x, v11.y);

            #pragma unroll
            for (int nt = 0; nt < 8; ++nt)
                mma_f16(acc[nt], a0, a1, a2, a3,
                        bf[nt >> 1][(nt & 1) * 2], bf[nt >> 1][(nt & 1) * 2 + 1]);
        }
    }

    // ---- epilogue: gate(r) * acc + bq --------------------------------------
    const float wr0 = Wr[0], wr1 = Wr[1], wr2 = Wr[2], wr3 = Wr[3];
    const float brv = br[0];

    const int rbase = bm * TM + w * 16 + (lane >> 2);
    #pragma unroll
    for (int h = 0; h < 2; ++h) {
        const int row = rbase + h * 8;
        const float rf = (float)rdat[row];
        float s = brv;
        s += fmaxf(1.0f - fabsf(0.0f - rf) * (1.0f / 3.0f), 0.0f) * wr0;
        s += fmaxf(1.0f - fabsf(1.0f - rf) * (1.0f / 3.0f), 0.0f) * wr1;
        s += fmaxf(1.0f - fabsf(2.0f - rf) * (1.0f / 3.0f), 0.0f) * wr2;
        s += fmaxf(1.0f - fabsf(3.0f - rf) * (1.0f / 3.0f), 0.0f) * wr3;
        const float gate = 1.0f / (1.0f + expf(-s));

        #pragma unroll
        for (int nt = 0; nt < 8; ++nt) {
            const int col = nt * 8 + (lane & 3) * 2;
            float2 v;
            v.x = acc[nt][h * 2 + 0] * gate + bq[col];
            v.y = acc[nt][h * 2 + 1] * gate + bq[col + 1];
            *reinterpret_cast<float2*>(out + (size_t)row * NDIM + col) = v;
        }
    }
}

// ---------------------------------------------------------------------------
// launch
// ---------------------------------------------------------------------------
typedef CUresult (*EncodeTiledFn)(
    CUtensorMap*, CUtensorMapDataType, cuuint32_t, void*,
    const cuuint64_t*, const cuuint64_t*, const cuuint32_t*, const cuuint32_t*,
    CUtensorMapInterleave, CUtensorMapSwizzle, CUtensorMapL2promotion,
    CUtensorMapFloatOOBfill);

extern "C" void kernel_launch(void* const* d_in, const int* in_sizes, int n_in,
                              void* d_out, int out_size) {
    const float* q    = (const float*)d_in[0];   // [64,512,800] f32
    const int*   rdat = (const int*)  d_in[1];   // [64,512]     i32
    const float* Wq   = (const float*)d_in[2];   // [64,800]     f32
    const float* bq   = (const float*)d_in[3];   // [64]         f32
    const float* Wr   = (const float*)d_in[4];   // [1,4]        f32
    const float* br   = (const float*)d_in[5];   // [1]          f32
    float* out = (float*)d_out;                  // [64,512,64]  f32

    static EncodeTiledFn encode = nullptr;
    if (!encode) {
        cudaDriverEntryPointQueryResult st;
        void* fn = nullptr;
        cudaGetDriverEntryPoint("cuTensorMapEncodeTiled", &fn,
                                cudaEnableDefault, &st);
        encode = (EncodeTiledFn)fn;
    }

    void* bImg = nullptr;
    cudaGetSymbolAddress(&bImg, g_Bt);

    // A: [KDIM, MDIM] f32, box [32, 128], SW128
    CUtensorMap tmapA{};
    {
        cuuint64_t dims[2]    = {KDIM, MDIM};
        cuuint64_t strides[1] = {KDIM * 4ull};
        cuuint32_t box[2]     = {TK, TM};
        cuuint32_t estr[2]    = {1, 1};
        encode(&tmapA, CU_TENSOR_MAP_DATA_TYPE_FLOAT32, 2, (void*)q,
               dims, strides, box, estr,
               CU_TENSOR_MAP_INTERLEAVE_NONE, CU_TENSOR_MAP_SWIZZLE_128B,
               CU_TENSOR_MAP_L2_PROMOTION_L2_256B,
               CU_TENSOR_MAP_FLOAT_OOB_FILL_NONE);
    }
    // B image: [256, 100] u32 rows of 1024B (stage s = rows [4s,4s+4)), box [256,4]
    CUtensorMap tmapB{};
    {
        cuuint64_t dims[2]    = {256, (cuuint64_t)(NIT * 4)};
        cuuint64_t strides[1] = {256 * 4ull};
        cuuint32_t box[2]     = {256, 4};
        cuuint32_t estr[2]    = {1, 1};
        encode(&tmapB, CU_TENSOR_MAP_DATA_TYPE_FLOAT32, 2, bImg,
               dims, strides, box, estr,
               CU_TENSOR_MAP_INTERLEAVE_NONE, CU_TENSOR_MAP_SWIZZLE_NONE,
               CU_TENSOR_MAP_L2_PROMOTION_L2_256B,
               CU_TENSOR_MAP_FLOAT_OOB_FILL_NONE);
    }

    convert_B_kernel<<<(NIT * 1024 + 255) / 256, 256>>>(Wq);

    cudaFuncSetAttribute(ordinal_embed_kernel,
                         cudaFuncAttributeMaxDynamicSharedMemorySize, SMEM_TOTAL);
    ordinal_embed_kernel<<<MDIM / TM, THREADS, SMEM_TOTAL>>>(
        tmapA, tmapB, rdat, bq, Wr, br, out);
}